// round 3
// baseline (speedup 1.0000x reference)
#include <cuda_runtime.h>
#include <cuda_bf16.h>
#include <math.h>

#define B_SZ  4
#define NSEQ  1024
#define DIMM  2048
#define NH    16
#define NKV   4
#define DH    128
#define MTOT  (B_SZ * NSEQ)

// ---------------- scratch (device globals: no allocation allowed) ----------
__device__ float g_Qh[B_SZ * NH  * NSEQ * DH];   // [b,h,n,d]  33.5 MB
__device__ float g_Kh[B_SZ * NKV * NSEQ * DH];   // [b,kv,n,d]  8.4 MB
__device__ float g_Vh[B_SZ * NKV * NSEQ * DH];   // [b,kv,n,d]  8.4 MB
__device__ float g_O [MTOT * DIMM];              // [b,n,h*d]  33.5 MB

// ---------------- SGEMM: C = A[MxK] @ B[KxN], 128x128x16 tiles -------------
// Double-buffered smem: load tile t+1 while computing tile t (1 bar/iter).
// HEAD_LAYOUT: write C into [b, head, n, d] layout (head = bn/128, block-const)
template <bool HEAD_LAYOUT>
__global__ __launch_bounds__(256)
void sgemm128(const float* __restrict__ A, const float* __restrict__ Bm,
              float* __restrict__ C, int M, int N, int K, int Hout)
{
    __shared__ float As[2][16 * 132];   // [k][m] transposed, padded
    __shared__ float Bs[2][16 * 132];   // [k][n], padded

    const int bm  = blockIdx.y * 128;
    const int bn  = blockIdx.x * 128;
    const int tid = threadIdx.x;
    const int tr  = tid >> 4;        // 0..15
    const int tc  = tid & 15;        // 0..15

    // per-thread load coords (2 chunks of 256 threads each covering 512 quads)
    const int ar0 = (tid + 0)   >> 2, ac0 = ((tid + 0)   & 3) * 4;
    const int ar1 = (tid + 256) >> 2, ac1 = ((tid + 256) & 3) * 4;
    const int br0 = (tid + 0)   >> 5, bc0 = ((tid + 0)   & 31) * 4;
    const int br1 = (tid + 256) >> 5, bc1 = ((tid + 256) & 31) * 4;

    float acc[8][8];
#pragma unroll
    for (int i = 0; i < 8; i++)
#pragma unroll
        for (int j = 0; j < 8; j++) acc[i][j] = 0.f;

    // prologue: load tile 0 into buffer 0
    {
        float4 av0 = *(const float4*)(A + (size_t)(bm + ar0) * K + ac0);
        float4 av1 = *(const float4*)(A + (size_t)(bm + ar1) * K + ac1);
        As[0][(ac0 + 0) * 132 + ar0] = av0.x;
        As[0][(ac0 + 1) * 132 + ar0] = av0.y;
        As[0][(ac0 + 2) * 132 + ar0] = av0.z;
        As[0][(ac0 + 3) * 132 + ar0] = av0.w;
        As[0][(ac1 + 0) * 132 + ar1] = av1.x;
        As[0][(ac1 + 1) * 132 + ar1] = av1.y;
        As[0][(ac1 + 2) * 132 + ar1] = av1.z;
        As[0][(ac1 + 3) * 132 + ar1] = av1.w;
        *(float4*)(Bs[0] + br0 * 132 + bc0) =
            *(const float4*)(Bm + (size_t)br0 * N + bn + bc0);
        *(float4*)(Bs[0] + br1 * 132 + bc1) =
            *(const float4*)(Bm + (size_t)br1 * N + bn + bc1);
    }
    __syncthreads();

    int p = 0;
    for (int kt = 0; kt < K; kt += 16, p ^= 1) {
        // prefetch next tile into registers (overlaps with compute below)
        float4 av0, av1, bv0, bv1;
        const bool more = (kt + 16) < K;
        if (more) {
            const int kn = kt + 16;
            av0 = *(const float4*)(A + (size_t)(bm + ar0) * K + kn + ac0);
            av1 = *(const float4*)(A + (size_t)(bm + ar1) * K + kn + ac1);
            bv0 = *(const float4*)(Bm + (size_t)(kn + br0) * N + bn + bc0);
            bv1 = *(const float4*)(Bm + (size_t)(kn + br1) * N + bn + bc1);
        }

        const float* Ap = As[p];
        const float* Bp = Bs[p];
#pragma unroll
        for (int kk = 0; kk < 16; kk++) {
            float4 a0 = *(const float4*)(Ap + kk * 132 + tr * 8);
            float4 a1 = *(const float4*)(Ap + kk * 132 + tr * 8 + 4);
            float4 b0 = *(const float4*)(Bp + kk * 132 + tc * 8);
            float4 b1 = *(const float4*)(Bp + kk * 132 + tc * 8 + 4);
            float a[8] = {a0.x, a0.y, a0.z, a0.w, a1.x, a1.y, a1.z, a1.w};
            float b[8] = {b0.x, b0.y, b0.z, b0.w, b1.x, b1.y, b1.z, b1.w};
#pragma unroll
            for (int i = 0; i < 8; i++)
#pragma unroll
                for (int j = 0; j < 8; j++) acc[i][j] += a[i] * b[j];
        }

        if (more) {
            const int q = p ^ 1;
            __syncthreads();   // everyone done reading buf q from 2 iters ago
            As[q][(ac0 + 0) * 132 + ar0] = av0.x;
            As[q][(ac0 + 1) * 132 + ar0] = av0.y;
            As[q][(ac0 + 2) * 132 + ar0] = av0.z;
            As[q][(ac0 + 3) * 132 + ar0] = av0.w;
            As[q][(ac1 + 0) * 132 + ar1] = av1.x;
            As[q][(ac1 + 1) * 132 + ar1] = av1.y;
            As[q][(ac1 + 2) * 132 + ar1] = av1.z;
            As[q][(ac1 + 3) * 132 + ar1] = av1.w;
            *(float4*)(Bs[q] + br0 * 132 + bc0) = bv0;
            *(float4*)(Bs[q] + br1 * 132 + bc1) = bv1;
            __syncthreads();
        }
    }

    if (HEAD_LAYOUT) {
        // col block bn covers exactly one head: h = bn>>7, d = tc*8+j
        const int h = bn >> 7;
#pragma unroll
        for (int i = 0; i < 8; i++) {
            int row = bm + tr * 8 + i;
            int b   = row >> 10, n = row & 1023;
            float* cp = C + (((size_t)(b * Hout + h)) * NSEQ + n) * DH + tc * 8;
            *(float4*)(cp)     = make_float4(acc[i][0], acc[i][1], acc[i][2], acc[i][3]);
            *(float4*)(cp + 4) = make_float4(acc[i][4], acc[i][5], acc[i][6], acc[i][7]);
        }
    } else {
#pragma unroll
        for (int i = 0; i < 8; i++) {
            int row = bm + tr * 8 + i;
            float* cp = C + (size_t)row * N + bn + tc * 8;
            *(float4*)(cp)     = make_float4(acc[i][0], acc[i][1], acc[i][2], acc[i][3]);
            *(float4*)(cp + 4) = make_float4(acc[i][4], acc[i][5], acc[i][6], acc[i][7]);
        }
    }
}

// ---------------- RoPE in-place on [bh, n, d] ------------------------------
__global__ void rope_kernel(float* __restrict__ t, int total)
{
    int idx = blockIdx.x * blockDim.x + threadIdx.x;
    if (idx >= total) return;
    int i  = idx & 63;
    int n  = (idx >> 6) & 1023;
    int bh = idx >> 16;                       // n*64 stride = 65536
    // inv_freq = 10000^(-i/64); accurate double-range-reduced angle
    double invf = exp(-(double)i * 0.14391156831212787);  // ln(10000)/64
    double ang  = fmod((double)n * invf, 6.283185307179586476925286766559);
    float s, c;
    sincosf((float)ang, &s, &c);
    float* p = t + (size_t)bh * (NSEQ * DH) + n * DH + i;
    float t1 = p[0], t2 = p[64];
    p[0]  = t1 * c - t2 * s;
    p[64] = t2 * c + t1 * s;
}

// ---------------- causal flash attention, 64x64 tiles ----------------------
// grid: (16 q-blocks, b*h). O written [b, n, h, d] and scaled by head_scale.
__global__ __launch_bounds__(256)
void flash_kernel(const float* __restrict__ Q, const float* __restrict__ K,
                  const float* __restrict__ V, const float* __restrict__ hsc,
                  float* __restrict__ O)
{
    extern __shared__ float sm[];
    float* Qs = sm;                 // 64*128, XOR-swizzled
    float* Ks = Qs + 64 * DH;
    float* Vs = Ks + 64 * DH;
    float* Ps = Vs + 64 * DH;       // 64*68

    const int qb  = (gridDim.x - 1) - blockIdx.x;  // big blocks first (balance)
    const int bh  = blockIdx.y;
    const int b   = bh >> 4, h = bh & 15;
    const int kvh = h >> 2;
    const int tid = threadIdx.x;
    const int tr  = tid >> 4, tc = tid & 15;
    const float scale = 0.08838834764831845f;      // 1/sqrt(128)

    const float* Qg = Q + ((size_t)(b * NH  + h  ) * NSEQ + qb * 64) * DH;
    const float* Kg = K + ((size_t)(b * NKV + kvh) * NSEQ) * DH;
    const float* Vg = V + ((size_t)(b * NKV + kvh) * NSEQ) * DH;

    // load Q tile (swizzle: float4-group col4 ^= (row>>2)&7)
    for (int t4 = tid; t4 < 64 * 32; t4 += 256) {
        int r = t4 >> 5, c4 = t4 & 31;
        float4 v = *(const float4*)(Qg + r * DH + c4 * 4);
        *(float4*)(Qs + r * DH + ((c4 ^ ((r >> 2) & 7)) << 2)) = v;
    }

    float m_i[4], l_i[4], o[4][8];
#pragma unroll
    for (int i = 0; i < 4; i++) {
        m_i[i] = -1e30f; l_i[i] = 0.f;
#pragma unroll
        for (int c = 0; c < 8; c++) o[i][c] = 0.f;
    }

    const int qsw = tr & 7;
    const int ksw = tc & 7;

    for (int kb = 0; kb <= qb; kb++) {
        __syncthreads();   // previous PV reads done before K/V overwrite
        const float* kg = Kg + (size_t)kb * 64 * DH;
        const float* vg = Vg + (size_t)kb * 64 * DH;
        for (int t4 = tid; t4 < 64 * 32; t4 += 256) {
            int r = t4 >> 5, c4 = t4 & 31;
            int sw = ((c4 ^ ((r >> 2) & 7)) << 2);
            *(float4*)(Ks + r * DH + sw) = *(const float4*)(kg + r * DH + c4 * 4);
            *(float4*)(Vs + r * DH + sw) = *(const float4*)(vg + r * DH + c4 * 4);
        }
        __syncthreads();

        // S = Q K^T (4x4 per thread)
        float s[4][4];
#pragma unroll
        for (int i = 0; i < 4; i++)
#pragma unroll
            for (int j = 0; j < 4; j++) s[i][j] = 0.f;

#pragma unroll 4
        for (int kk4 = 0; kk4 < 32; kk4++) {
            float4 qv[4], kv[4];
#pragma unroll
            for (int i = 0; i < 4; i++)
                qv[i] = *(float4*)(Qs + (tr * 4 + i) * DH + ((kk4 ^ qsw) << 2));
#pragma unroll
            for (int j = 0; j < 4; j++)
                kv[j] = *(float4*)(Ks + (tc * 4 + j) * DH + ((kk4 ^ ksw) << 2));
#pragma unroll
            for (int i = 0; i < 4; i++)
#pragma unroll
                for (int j = 0; j < 4; j++) {
                    s[i][j] += qv[i].x * kv[j].x;
                    s[i][j] += qv[i].y * kv[j].y;
                    s[i][j] += qv[i].z * kv[j].z;
                    s[i][j] += qv[i].w * kv[j].w;
                }
        }

        const bool diag = (kb == qb);
#pragma unroll
        for (int i = 0; i < 4; i++) {
            int row = tr * 4 + i;
            float mx = -1e30f;
#pragma unroll
            for (int j = 0; j < 4; j++) {
                float sv = s[i][j] * scale;
                if (diag && (tc * 4 + j) > row) sv = -1e30f;
                s[i][j] = sv;
                mx = fmaxf(mx, sv);
            }
            mx = fmaxf(mx, __shfl_xor_sync(0xffffffffu, mx, 8));
            mx = fmaxf(mx, __shfl_xor_sync(0xffffffffu, mx, 4));
            mx = fmaxf(mx, __shfl_xor_sync(0xffffffffu, mx, 2));
            mx = fmaxf(mx, __shfl_xor_sync(0xffffffffu, mx, 1));
            float mn    = fmaxf(m_i[i], mx);
            float alpha = __expf(m_i[i] - mn);
            m_i[i] = mn;
            float rs = 0.f;
#pragma unroll
            for (int j = 0; j < 4; j++) {
                float p = __expf(s[i][j] - mn);
                s[i][j] = p;
                rs += p;
            }
            rs += __shfl_xor_sync(0xffffffffu, rs, 8);
            rs += __shfl_xor_sync(0xffffffffu, rs, 4);
            rs += __shfl_xor_sync(0xffffffffu, rs, 2);
            rs += __shfl_xor_sync(0xffffffffu, rs, 1);
            l_i[i] = l_i[i] * alpha + rs;
#pragma unroll
            for (int c = 0; c < 8; c++) o[i][c] *= alpha;
#pragma unroll
            for (int j = 0; j < 4; j++) Ps[row * 68 + tc * 4 + j] = s[i][j];
        }
        __syncthreads();

        // O += P @ V   (O cols interleaved: c = tc + 16*cc -> conflict-free V)
#pragma unroll 4
        for (int j = 0; j < 64; j++) {
            float pv[4];
#pragma unroll
            for (int i = 0; i < 4; i++) pv[i] = Ps[(tr * 4 + i) * 68 + j];
            const int jsw = (j >> 2) & 7;
            float vv[8];
#pragma unroll
            for (int cc = 0; cc < 8; cc++) {
                int c = tc + cc * 16;
                vv[cc] = Vs[j * DH + ((((c >> 2) ^ jsw)) << 2) + (c & 3)];
            }
#pragma unroll
            for (int i = 0; i < 4; i++)
#pragma unroll
                for (int cc = 0; cc < 8; cc++) o[i][cc] += pv[i] * vv[cc];
        }
    }

    const float hval = hsc[h];
#pragma unroll
    for (int i = 0; i < 4; i++) {
        int   n   = qb * 64 + tr * 4 + i;
        float inv = hval / l_i[i];
        float* op = O + ((size_t)(b * NSEQ + n)) * DIMM + h * DH;
#pragma unroll
        for (int cc = 0; cc < 8; cc++) op[tc + cc * 16] = o[i][cc] * inv;
    }
}

// ---------------- launch ---------------------------------------------------
extern "C" void kernel_launch(void* const* d_in, const int* in_sizes, int n_in,
                              void* d_out, int out_size)
{
    const float* x   = (const float*)d_in[0];
    const float* Wq  = (const float*)d_in[1];
    const float* Wk  = (const float*)d_in[2];
    const float* Wv  = (const float*)d_in[3];
    const float* Wo  = (const float*)d_in[4];
    const float* hsc = (const float*)d_in[5];
    float* out = (float*)d_out;

    float *Qh, *Kh, *Vh, *Oat;
    cudaGetSymbolAddress((void**)&Qh,  g_Qh);
    cudaGetSymbolAddress((void**)&Kh,  g_Kh);
    cudaGetSymbolAddress((void**)&Vh,  g_Vh);
    cudaGetSymbolAddress((void**)&Oat, g_O);

    // QKV projections (head-layout stores)
    sgemm128<true><<<dim3(16, 32), 256>>>(x, Wq, Qh, MTOT, 2048, DIMM, NH);
    sgemm128<true><<<dim3(4,  32), 256>>>(x, Wk, Kh, MTOT, 512,  DIMM, NKV);
    sgemm128<true><<<dim3(4,  32), 256>>>(x, Wv, Vh, MTOT, 512,  DIMM, NKV);

    // RoPE on Q and K
    int ropeQ = NH  * B_SZ * NSEQ * 64;
    int ropeK = NKV * B_SZ * NSEQ * 64;
    rope_kernel<<<ropeQ / 256, 256>>>(Qh, ropeQ);
    rope_kernel<<<ropeK / 256, 256>>>(Kh, ropeK);

    // flash attention
    size_t smem = (size_t)(3 * 64 * DH + 64 * 68) * sizeof(float); // 115712 B
    cudaFuncSetAttribute(flash_kernel,
                         cudaFuncAttributeMaxDynamicSharedMemorySize, (int)smem);
    flash_kernel<<<dim3(16, B_SZ * NH), 256, smem>>>(Qh, Kh, Vh, hsc, Oat);

    // output projection
    sgemm128<false><<<dim3(16, 32), 256>>>(Oat, Wo, out, MTOT, 2048, DIMM, 0);
}

// round 8
// speedup vs baseline: 1.9216x; 1.9216x over previous
#include <cuda_runtime.h>
#include <cuda_bf16.h>
#include <math.h>
#include <stdint.h>

#define B_SZ  4
#define NSEQ  1024
#define DIMM  2048
#define KDIM  2048
#define NH    16
#define NKV   4
#define DH    128
#define MTOT  (B_SZ * NSEQ)

// ---------------- scratch (device globals: no allocation allowed) ----------
__device__ float g_Qh[B_SZ * NH  * NSEQ * DH];     // fp32 [b,h,n,d]
__device__ float g_Kh[B_SZ * NKV * NSEQ * DH];
__device__ float g_Vh[B_SZ * NKV * NSEQ * DH];
__device__ __nv_bfloat16 g_xhi[MTOT * KDIM], g_xlo[MTOT * KDIM];
__device__ __nv_bfloat16 g_Wqh[2048 * KDIM], g_Wql[2048 * KDIM];   // W^T [n][k]
__device__ __nv_bfloat16 g_Wkh[512  * KDIM], g_Wkl[512  * KDIM];
__device__ __nv_bfloat16 g_Wvh[512  * KDIM], g_Wvl[512  * KDIM];
__device__ __nv_bfloat16 g_Woh[2048 * KDIM], g_Wol[2048 * KDIM];
__device__ __nv_bfloat16 g_Ohi[MTOT * DIMM], g_Olo[MTOT * DIMM];
__device__ float g_cs[NSEQ * 64 * 2];              // rope cos/sin table

// ---------------- helpers ---------------------------------------------------
__device__ __forceinline__ uint32_t cvta_s(const void* p) {
    uint32_t a;
    asm("{ .reg .u64 t; cvta.to.shared.u64 t, %1; cvt.u32.u64 %0, t; }"
        : "=r"(a) : "l"(p));
    return a;
}
__device__ __forceinline__ void cp16(uint32_t dst, const void* src) {
    asm volatile("cp.async.cg.shared.global [%0], [%1], 16;"
                 :: "r"(dst), "l"(src) : "memory");
}
__device__ __forceinline__ void ldsm4(uint32_t* r, uint32_t addr) {
    asm volatile("ldmatrix.sync.aligned.m8n8.x4.shared.b16 {%0,%1,%2,%3}, [%4];"
                 : "=r"(r[0]), "=r"(r[1]), "=r"(r[2]), "=r"(r[3]) : "r"(addr));
}
__device__ __forceinline__ void mma16816(float* d, const uint32_t* a,
                                         const uint32_t* b) {
    asm volatile(
        "mma.sync.aligned.m16n8k16.row.col.f32.bf16.bf16.f32 "
        "{%0,%1,%2,%3}, {%4,%5,%6,%7}, {%8,%9}, {%0,%1,%2,%3};"
        : "+f"(d[0]), "+f"(d[1]), "+f"(d[2]), "+f"(d[3])
        : "r"(a[0]), "r"(a[1]), "r"(a[2]), "r"(a[3]), "r"(b[0]), "r"(b[1]));
}

// ---------------- prep: fp32 -> bf16 hi/lo split ---------------------------
__global__ __launch_bounds__(256) void prep_split(const float* __restrict__ x,
                                                  __nv_bfloat16* __restrict__ hi,
                                                  __nv_bfloat16* __restrict__ lo,
                                                  int n4)
{
    int idx = blockIdx.x * blockDim.x + threadIdx.x;
    if (idx >= n4) return;
    float4 v = ((const float4*)x)[idx];
    __nv_bfloat16 h0 = __float2bfloat16(v.x), h1 = __float2bfloat16(v.y);
    __nv_bfloat16 h2 = __float2bfloat16(v.z), h3 = __float2bfloat16(v.w);
    __nv_bfloat162* hp = (__nv_bfloat162*)hi;
    __nv_bfloat162* lp = (__nv_bfloat162*)lo;
    hp[2*idx]   = __nv_bfloat162(h0, h1);
    hp[2*idx+1] = __nv_bfloat162(h2, h3);
    lp[2*idx]   = __nv_bfloat162(__float2bfloat16(v.x - __bfloat162float(h0)),
                                 __float2bfloat16(v.y - __bfloat162float(h1)));
    lp[2*idx+1] = __nv_bfloat162(__float2bfloat16(v.z - __bfloat162float(h2)),
                                 __float2bfloat16(v.w - __bfloat162float(h3)));
}

// ---------------- prep: W[K][N] -> W^T[n][k] bf16 hi/lo --------------------
__global__ __launch_bounds__(256) void wtrans(const float* __restrict__ W,
                                              __nv_bfloat16* __restrict__ thi,
                                              __nv_bfloat16* __restrict__ tlo, int N)
{
    __shared__ float t[32][33];
    int n0 = blockIdx.x * 32, k0 = blockIdx.y * 32;
    int tx = threadIdx.x & 31, ty = threadIdx.x >> 5;
#pragma unroll
    for (int j = 0; j < 32; j += 8)
        t[ty + j][tx] = W[(size_t)(k0 + ty + j) * N + n0 + tx];
    __syncthreads();
#pragma unroll
    for (int j = 0; j < 32; j += 8) {
        float v = t[tx][ty + j];
        __nv_bfloat16 h = __float2bfloat16(v);
        size_t o = (size_t)(n0 + ty + j) * KDIM + k0 + tx;
        thi[o] = h;
        tlo[o] = __float2bfloat16(v - __bfloat162float(h));
    }
}

// ---------------- mma.sync GEMM: C[M,N] = A @ B^T (B stored [N][K]) --------
// A = Ahi+Alo, B = Bhi+Blo bf16; 3-pass hi/lo. 128x128 CTA tile, K-stage 64.
// 8 warps as 4(m) x 2(n): warp tile 32x64. cp.async double-buffered smem.
// smem stage layout (64KB): Ahi[128][64] | Alo | Bhi[128][64] | Blo (16KB each)
// rows 128B, 16B-chunk XOR swizzle: phys_chunk = c4 ^ (row & 7).
template <bool HEAD>
__global__ __launch_bounds__(256)
void gemm_mma(const __nv_bfloat16* __restrict__ Ahi, const __nv_bfloat16* __restrict__ Alo,
              const __nv_bfloat16* __restrict__ Bhi, const __nv_bfloat16* __restrict__ Blo,
              float* __restrict__ C, int Nglob, int Hout)
{
    extern __shared__ __align__(16) char smem[];
    const uint32_t sb0 = cvta_s(smem);

    const int tid  = threadIdx.x;
    const int wid  = tid >> 5, lane = tid & 31;
    const int wm   = wid & 3,  wn   = wid >> 2;        // 4 x 2 warps
    const int am   = wm * 32,  bn0  = wn * 64;
    const int bm   = blockIdx.y * 128, bn = blockIdx.x * 128;

    const __nv_bfloat16* srcs[4] = { Ahi + (size_t)bm * KDIM, Alo + (size_t)bm * KDIM,
                                     Bhi + (size_t)bn * KDIM, Blo + (size_t)bn * KDIM };

    // per-thread load coords: 1024 16B-chunks per 16KB tile, 4 per thread
    const int lr[4] = { (tid + 0)   >> 3, (tid + 256) >> 3,
                        (tid + 512) >> 3, (tid + 768) >> 3 };
    const int lc[4] = { (tid + 0)   & 7,  (tid + 256) & 7,
                        (tid + 512) & 7,  (tid + 768) & 7 };

    float acc[2][8][4];
#pragma unroll
    for (int mi = 0; mi < 2; mi++)
#pragma unroll
        for (int ni = 0; ni < 8; ni++)
#pragma unroll
            for (int c = 0; c < 4; c++) acc[mi][ni][c] = 0.f;

    const int NT = KDIM / 64;   // 32 k-stages

    // issue loads for stage s of k-tile kt
    auto load_stage = [&](int s, int kt) {
        uint32_t sb = sb0 + s * 65536;
#pragma unroll
        for (int tt = 0; tt < 4; tt++) {
            const __nv_bfloat16* src = srcs[tt];
#pragma unroll
            for (int a = 0; a < 4; a++) {
                int r = lr[a], c4 = lc[a];
                uint32_t dst = sb + tt * 16384 + r * 128 + ((c4 ^ (r & 7)) << 4);
                cp16(dst, src + (size_t)r * KDIM + kt + c4 * 8);
            }
        }
        asm volatile("cp.async.commit_group;" ::: "memory");
    };

    load_stage(0, 0);

    for (int it = 0; it < NT; ++it) {
        if (it + 1 < NT) {
            load_stage((it + 1) & 1, (it + 1) * 64);
            asm volatile("cp.async.wait_group 1;" ::: "memory");
        } else {
            asm volatile("cp.async.wait_group 0;" ::: "memory");
        }
        __syncthreads();

        const uint32_t sb = sb0 + (it & 1) * 65536;
#pragma unroll
        for (int ks = 0; ks < 4; ks++) {
            uint32_t ah[2][4], al[2][4], bh[8][2], bl[8][2];
#pragma unroll
            for (int mi = 0; mi < 2; mi++) {
                int r  = am + mi * 16 + (lane & 15);
                int c4 = ks * 2 + (lane >> 4);
                uint32_t off = r * 128 + ((c4 ^ (r & 7)) << 4);
                ldsm4(ah[mi], sb + off);             // Ahi
                ldsm4(al[mi], sb + 16384 + off);     // Alo
            }
#pragma unroll
            for (int nb = 0; nb < 4; nb++) {
                int r  = bn0 + nb * 16 + (lane & 15);
                int c4 = ks * 2 + (lane >> 4);
                uint32_t off = r * 128 + ((c4 ^ (r & 7)) << 4);
                uint32_t t[4];
                ldsm4(t, sb + 32768 + off);          // Bhi
                bh[nb*2][0] = t[0]; bh[nb*2][1] = t[2];
                bh[nb*2+1][0] = t[1]; bh[nb*2+1][1] = t[3];
                ldsm4(t, sb + 49152 + off);          // Blo
                bl[nb*2][0] = t[0]; bl[nb*2][1] = t[2];
                bl[nb*2+1][0] = t[1]; bl[nb*2+1][1] = t[3];
            }
#pragma unroll
            for (int mi = 0; mi < 2; mi++)
#pragma unroll
                for (int ni = 0; ni < 8; ni++) mma16816(acc[mi][ni], ah[mi], bh[ni]);
#pragma unroll
            for (int mi = 0; mi < 2; mi++)
#pragma unroll
                for (int ni = 0; ni < 8; ni++) mma16816(acc[mi][ni], al[mi], bh[ni]);
#pragma unroll
            for (int mi = 0; mi < 2; mi++)
#pragma unroll
                for (int ni = 0; ni < 8; ni++) mma16816(acc[mi][ni], ah[mi], bl[ni]);
        }
        __syncthreads();
    }

    // epilogue: c0,c1 -> (row g, col tig*2), c2,c3 -> (row g+8)
    const int g = lane >> 2, tig = lane & 3;
#pragma unroll
    for (int mi = 0; mi < 2; mi++) {
#pragma unroll
        for (int ni = 0; ni < 8; ni++) {
            int d   = bn0 + ni * 8 + tig * 2;
            int r0  = bm + am + mi * 16 + g;
            int r1  = r0 + 8;
            float* p0;
            float* p1;
            if (HEAD) {
                int h = bn >> 7;
                int b0 = r0 >> 10, n0 = r0 & 1023;
                int b1 = r1 >> 10, n1 = r1 & 1023;
                p0 = C + (((size_t)(b0 * Hout + h)) * NSEQ + n0) * DH + d;
                p1 = C + (((size_t)(b1 * Hout + h)) * NSEQ + n1) * DH + d;
            } else {
                p0 = C + (size_t)r0 * Nglob + bn + d;
                p1 = C + (size_t)r1 * Nglob + bn + d;
            }
            *(float2*)p0 = make_float2(acc[mi][ni][0], acc[mi][ni][1]);
            *(float2*)p1 = make_float2(acc[mi][ni][2], acc[mi][ni][3]);
        }
    }
}

// ---------------- rope: table (accurate, tiny) + apply ---------------------
__global__ void rope_table(float* __restrict__ cs)
{
    int idx = blockIdx.x * blockDim.x + threadIdx.x;   // n*64 + i
    if (idx >= NSEQ * 64) return;
    int i = idx & 63, n = idx >> 6;
    double invf = exp(-(double)i * 0.14391156831212787);  // ln(10000)/64
    double ang  = (double)n * invf;
    double s, c;
    sincos(ang, &s, &c);
    cs[idx * 2]     = (float)c;
    cs[idx * 2 + 1] = (float)s;
}
__global__ void rope_apply(float* __restrict__ t, const float* __restrict__ cs, int total)
{
    int idx = blockIdx.x * blockDim.x + threadIdx.x;
    if (idx >= total) return;
    int i  = idx & 63;
    int n  = (idx >> 6) & 1023;
    int bh = idx >> 16;
    float2 v = ((const float2*)cs)[n * 64 + i];
    float* p = t + (size_t)bh * (NSEQ * DH) + n * DH + i;
    float t1 = p[0], t2 = p[64];
    p[0]  = t1 * v.x - t2 * v.y;
    p[64] = t2 * v.x + t1 * v.y;
}

// ---------------- causal flash attention, 64x64 tiles (fp32) ---------------
__global__ __launch_bounds__(256)
void flash_kernel(const float* __restrict__ Q, const float* __restrict__ K,
                  const float* __restrict__ V, const float* __restrict__ hsc,
                  __nv_bfloat16* __restrict__ Ohi, __nv_bfloat16* __restrict__ Olo)
{
    extern __shared__ float smf[];
    float* Qs = smf;
    float* Ks = Qs + 64 * DH;
    float* Vs = Ks + 64 * DH;
    float* Ps = Vs + 64 * DH;

    const int qb  = (gridDim.x - 1) - blockIdx.x;
    const int bh  = blockIdx.y;
    const int b   = bh >> 4, h = bh & 15;
    const int kvh = h >> 2;
    const int tid = threadIdx.x;
    const int tr  = tid >> 4, tc = tid & 15;
    const float scale = 0.08838834764831845f;

    const float* Qg = Q + ((size_t)(b * NH  + h  ) * NSEQ + qb * 64) * DH;
    const float* Kg = K + ((size_t)(b * NKV + kvh) * NSEQ) * DH;
    const float* Vg = V + ((size_t)(b * NKV + kvh) * NSEQ) * DH;

    for (int t4 = tid; t4 < 64 * 32; t4 += 256) {
        int r = t4 >> 5, c4 = t4 & 31;
        float4 v = *(const float4*)(Qg + r * DH + c4 * 4);
        *(float4*)(Qs + r * DH + ((c4 ^ ((r >> 2) & 7)) << 2)) = v;
    }

    float m_i[4], l_i[4], o[4][8];
#pragma unroll
    for (int i = 0; i < 4; i++) {
        m_i[i] = -1e30f; l_i[i] = 0.f;
#pragma unroll
        for (int c = 0; c < 8; c++) o[i][c] = 0.f;
    }
    const int qsw = tr & 7, ksw = tc & 7;

    for (int kb = 0; kb <= qb; kb++) {
        __syncthreads();
        const float* kg = Kg + (size_t)kb * 64 * DH;
        const float* vg = Vg + (size_t)kb * 64 * DH;
        for (int t4 = tid; t4 < 64 * 32; t4 += 256) {
            int r = t4 >> 5, c4 = t4 & 31;
            int sw = ((c4 ^ ((r >> 2) & 7)) << 2);
            *(float4*)(Ks + r * DH + sw) = *(const float4*)(kg + r * DH + c4 * 4);
            *(float4*)(Vs + r * DH + sw) = *(const float4*)(vg + r * DH + c4 * 4);
        }
        __syncthreads();

        float s[4][4];
#pragma unroll
        for (int i = 0; i < 4; i++)
#pragma unroll
            for (int j = 0; j < 4; j++) s[i][j] = 0.f;
#pragma unroll 4
        for (int kk4 = 0; kk4 < 32; kk4++) {
            float4 qv[4], kv[4];
#pragma unroll
            for (int i = 0; i < 4; i++)
                qv[i] = *(float4*)(Qs + (tr * 4 + i) * DH + ((kk4 ^ qsw) << 2));
#pragma unroll
            for (int j = 0; j < 4; j++)
                kv[j] = *(float4*)(Ks + (tc * 4 + j) * DH + ((kk4 ^ ksw) << 2));
#pragma unroll
            for (int i = 0; i < 4; i++)
#pragma unroll
                for (int j = 0; j < 4; j++) {
                    s[i][j] += qv[i].x * kv[j].x;
                    s[i][j] += qv[i].y * kv[j].y;
                    s[i][j] += qv[i].z * kv[j].z;
                    s[i][j] += qv[i].w * kv[j].w;
                }
        }

        const bool diag = (kb == qb);
#pragma unroll
        for (int i = 0; i < 4; i++) {
            int row = tr * 4 + i;
            float mx = -1e30f;
#pragma unroll
            for (int j = 0; j < 4; j++) {
                float sv = s[i][j] * scale;
                if (diag && (tc * 4 + j) > row) sv = -1e30f;
                s[i][j] = sv;
                mx = fmaxf(mx, sv);
            }
            mx = fmaxf(mx, __shfl_xor_sync(0xffffffffu, mx, 8));
            mx = fmaxf(mx, __shfl_xor_sync(0xffffffffu, mx, 4));
            mx = fmaxf(mx, __shfl_xor_sync(0xffffffffu, mx, 2));
            mx = fmaxf(mx, __shfl_xor_sync(0xffffffffu, mx, 1));
            float mn    = fmaxf(m_i[i], mx);
            float alpha = __expf(m_i[i] - mn);
            m_i[i] = mn;
            float rs = 0.f;
#pragma unroll
            for (int j = 0; j < 4; j++) {
                float p = __expf(s[i][j] - mn);
                s[i][j] = p;
                rs += p;
            }
            rs += __shfl_xor_sync(0xffffffffu, rs, 8);
            rs += __shfl_xor_sync(0xffffffffu, rs, 4);
            rs += __shfl_xor_sync(0xffffffffu, rs, 2);
            rs += __shfl_xor_sync(0xffffffffu, rs, 1);
            l_i[i] = l_i[i] * alpha + rs;
#pragma unroll
            for (int c = 0; c < 8; c++) o[i][c] *= alpha;
#pragma unroll
            for (int j = 0; j < 4; j++) Ps[row * 68 + tc * 4 + j] = s[i][j];
        }
        __syncthreads();

#pragma unroll 4
        for (int j = 0; j < 64; j++) {
            float pv[4];
#pragma unroll
            for (int i = 0; i < 4; i++) pv[i] = Ps[(tr * 4 + i) * 68 + j];
            const int jsw = (j >> 2) & 7;
            float vv[8];
#pragma unroll
            for (int cc = 0; cc < 8; cc++) {
                int c = tc + cc * 16;
                vv[cc] = Vs[j * DH + ((((c >> 2) ^ jsw)) << 2) + (c & 3)];
            }
#pragma unroll
            for (int i = 0; i < 4; i++)
#pragma unroll
                for (int cc = 0; cc < 8; cc++) o[i][cc] += pv[i] * vv[cc];
        }
    }

    const float hval = hsc[h];
#pragma unroll
    for (int i = 0; i < 4; i++) {
        int   n   = qb * 64 + tr * 4 + i;
        float inv = hval / l_i[i];
        size_t base = ((size_t)(b * NSEQ + n)) * DIMM + h * DH;
#pragma unroll
        for (int cc = 0; cc < 8; cc++) {
            float val = o[i][cc] * inv;
            __nv_bfloat16 hh = __float2bfloat16(val);
            Ohi[base + tc + cc * 16] = hh;
            Olo[base + tc + cc * 16] = __float2bfloat16(val - __bfloat162float(hh));
        }
    }
}

// ---------------- launch ---------------------------------------------------
extern "C" void kernel_launch(void* const* d_in, const int* in_sizes, int n_in,
                              void* d_out, int out_size)
{
    const float* x   = (const float*)d_in[0];
    const float* Wq  = (const float*)d_in[1];
    const float* Wk  = (const float*)d_in[2];
    const float* Wv  = (const float*)d_in[3];
    const float* Wo  = (const float*)d_in[4];
    const float* hsc = (const float*)d_in[5];
    float* out = (float*)d_out;

    float *Qh, *Kh, *Vh, *cs;
    __nv_bfloat16 *xhi, *xlo, *Wqh, *Wql, *Wkh, *Wkl, *Wvh, *Wvl, *Woh, *Wol, *Ohi, *Olo;
    cudaGetSymbolAddress((void**)&Qh,  g_Qh);
    cudaGetSymbolAddress((void**)&Kh,  g_Kh);
    cudaGetSymbolAddress((void**)&Vh,  g_Vh);
    cudaGetSymbolAddress((void**)&cs,  g_cs);
    cudaGetSymbolAddress((void**)&xhi, g_xhi);  cudaGetSymbolAddress((void**)&xlo, g_xlo);
    cudaGetSymbolAddress((void**)&Wqh, g_Wqh);  cudaGetSymbolAddress((void**)&Wql, g_Wql);
    cudaGetSymbolAddress((void**)&Wkh, g_Wkh);  cudaGetSymbolAddress((void**)&Wkl, g_Wkl);
    cudaGetSymbolAddress((void**)&Wvh, g_Wvh);  cudaGetSymbolAddress((void**)&Wvl, g_Wvl);
    cudaGetSymbolAddress((void**)&Woh, g_Woh);  cudaGetSymbolAddress((void**)&Wol, g_Wol);
    cudaGetSymbolAddress((void**)&Ohi, g_Ohi);  cudaGetSymbolAddress((void**)&Olo, g_Olo);

    // prep
    rope_table<<<(NSEQ * 64 + 255) / 256, 256>>>(cs);
    prep_split<<<(MTOT * KDIM / 4 + 255) / 256, 256>>>(x, xhi, xlo, MTOT * KDIM / 4);
    wtrans<<<dim3(64, 64), 256>>>(Wq, Wqh, Wql, 2048);
    wtrans<<<dim3(16, 64), 256>>>(Wk, Wkh, Wkl, 512);
    wtrans<<<dim3(16, 64), 256>>>(Wv, Wvh, Wvl, 512);
    wtrans<<<dim3(64, 64), 256>>>(Wo, Woh, Wol, 2048);

    // mma.sync GEMMs (double-buffered cp.async: 128KB dynamic smem)
    const int gsm = 131072;
    cudaFuncSetAttribute(gemm_mma<true>,  cudaFuncAttributeMaxDynamicSharedMemorySize, gsm);
    cudaFuncSetAttribute(gemm_mma<false>, cudaFuncAttributeMaxDynamicSharedMemorySize, gsm);
    gemm_mma<true><<<dim3(16, 32), 256, gsm>>>(xhi, xlo, Wqh, Wql, Qh, 2048, NH);
    gemm_mma<true><<<dim3(4,  32), 256, gsm>>>(xhi, xlo, Wkh, Wkl, Kh, 512,  NKV);
    gemm_mma<true><<<dim3(4,  32), 256, gsm>>>(xhi, xlo, Wvh, Wvl, Vh, 512,  NKV);

    // rope
    int ropeQ = NH  * B_SZ * NSEQ * 64;
    int ropeK = NKV * B_SZ * NSEQ * 64;
    rope_apply<<<ropeQ / 256, 256>>>(Qh, cs, ropeQ);
    rope_apply<<<ropeK / 256, 256>>>(Kh, cs, ropeK);

    // flash attention (fp32, writes bf16 hi/lo O)
    size_t fsm = (size_t)(3 * 64 * DH + 64 * 68) * sizeof(float);
    cudaFuncSetAttribute(flash_kernel,
                         cudaFuncAttributeMaxDynamicSharedMemorySize, (int)fsm);
    flash_kernel<<<dim3(16, B_SZ * NH), 256, fsm>>>(Qh, Kh, Vh, hsc, Ohi, Olo);

    // output projection
    gemm_mma<false><<<dim3(16, 32), 256, gsm>>>(Ohi, Olo, Woh, Wol, out, 2048, 0);
}

// round 9
// speedup vs baseline: 2.8565x; 1.4865x over previous
#include <cuda_runtime.h>
#include <cuda_bf16.h>
#include <math.h>
#include <stdint.h>

#define B_SZ  4
#define NSEQ  1024
#define DIMM  2048
#define KDIM  2048
#define NH    16
#define NKV   4
#define DH    128
#define MTOT  (B_SZ * NSEQ)

// ---------------- scratch (device globals: no allocation allowed) ----------
__device__ float g_Qh[B_SZ * NH  * NSEQ * DH];     // fp32 [b,h,n,d]
__device__ float g_Kh[B_SZ * NKV * NSEQ * DH];
__device__ float g_Vh[B_SZ * NKV * NSEQ * DH];
__device__ __nv_bfloat16 g_xhi[MTOT * KDIM], g_xlo[MTOT * KDIM];
__device__ __nv_bfloat16 g_Wqh[2048 * KDIM], g_Wql[2048 * KDIM];   // W^T [n][k]
__device__ __nv_bfloat16 g_Wkh[512  * KDIM], g_Wkl[512  * KDIM];
__device__ __nv_bfloat16 g_Wvh[512  * KDIM], g_Wvl[512  * KDIM];
__device__ __nv_bfloat16 g_Woh[2048 * KDIM], g_Wol[2048 * KDIM];
__device__ __nv_bfloat16 g_Ohi[MTOT * DIMM], g_Olo[MTOT * DIMM];
__device__ __nv_bfloat16 g_Qbh[B_SZ * NH  * NSEQ * DH], g_Qbl[B_SZ * NH  * NSEQ * DH];
__device__ __nv_bfloat16 g_Kbh[B_SZ * NKV * NSEQ * DH], g_Kbl[B_SZ * NKV * NSEQ * DH];
__device__ __nv_bfloat16 g_Vbh[B_SZ * NKV * NSEQ * DH], g_Vbl[B_SZ * NKV * NSEQ * DH];
__device__ float g_cs[NSEQ * 64 * 2];              // rope cos/sin table

// ---------------- helpers ---------------------------------------------------
__device__ __forceinline__ uint32_t cvta_s(const void* p) {
    uint32_t a;
    asm("{ .reg .u64 t; cvta.to.shared.u64 t, %1; cvt.u32.u64 %0, t; }"
        : "=r"(a) : "l"(p));
    return a;
}
__device__ __forceinline__ void cp16(uint32_t dst, const void* src) {
    asm volatile("cp.async.cg.shared.global [%0], [%1], 16;"
                 :: "r"(dst), "l"(src) : "memory");
}
__device__ __forceinline__ void ldsm4(uint32_t* r, uint32_t addr) {
    asm volatile("ldmatrix.sync.aligned.m8n8.x4.shared.b16 {%0,%1,%2,%3}, [%4];"
                 : "=r"(r[0]), "=r"(r[1]), "=r"(r[2]), "=r"(r[3]) : "r"(addr));
}
__device__ __forceinline__ void ldsm4t(uint32_t* r, uint32_t addr) {
    asm volatile("ldmatrix.sync.aligned.m8n8.x4.trans.shared.b16 {%0,%1,%2,%3}, [%4];"
                 : "=r"(r[0]), "=r"(r[1]), "=r"(r[2]), "=r"(r[3]) : "r"(addr));
}
__device__ __forceinline__ void mma16816(float* d, const uint32_t* a,
                                         const uint32_t* b) {
    asm volatile(
        "mma.sync.aligned.m16n8k16.row.col.f32.bf16.bf16.f32 "
        "{%0,%1,%2,%3}, {%4,%5,%6,%7}, {%8,%9}, {%0,%1,%2,%3};"
        : "+f"(d[0]), "+f"(d[1]), "+f"(d[2]), "+f"(d[3])
        : "r"(a[0]), "r"(a[1]), "r"(a[2]), "r"(a[3]), "r"(b[0]), "r"(b[1]));
}

// ---------------- prep: fp32 -> bf16 hi/lo split ---------------------------
__global__ __launch_bounds__(256) void prep_split(const float* __restrict__ x,
                                                  __nv_bfloat16* __restrict__ hi,
                                                  __nv_bfloat16* __restrict__ lo,
                                                  int n4)
{
    int idx = blockIdx.x * blockDim.x + threadIdx.x;
    if (idx >= n4) return;
    float4 v = ((const float4*)x)[idx];
    __nv_bfloat16 h0 = __float2bfloat16(v.x), h1 = __float2bfloat16(v.y);
    __nv_bfloat16 h2 = __float2bfloat16(v.z), h3 = __float2bfloat16(v.w);
    __nv_bfloat162* hp = (__nv_bfloat162*)hi;
    __nv_bfloat162* lp = (__nv_bfloat162*)lo;
    hp[2*idx]   = __nv_bfloat162(h0, h1);
    hp[2*idx+1] = __nv_bfloat162(h2, h3);
    lp[2*idx]   = __nv_bfloat162(__float2bfloat16(v.x - __bfloat162float(h0)),
                                 __float2bfloat16(v.y - __bfloat162float(h1)));
    lp[2*idx+1] = __nv_bfloat162(__float2bfloat16(v.z - __bfloat162float(h2)),
                                 __float2bfloat16(v.w - __bfloat162float(h3)));
}

// ---------------- prep: all 4 weights W[K][N] -> W^T[n][k] bf16 hi/lo ------
__global__ __launch_bounds__(256) void wtrans_all(
    const float* __restrict__ Wq, const float* __restrict__ Wk,
    const float* __restrict__ Wv, const float* __restrict__ Wo,
    __nv_bfloat16* qh, __nv_bfloat16* ql, __nv_bfloat16* kh, __nv_bfloat16* kl,
    __nv_bfloat16* vh, __nv_bfloat16* vl, __nv_bfloat16* oh, __nv_bfloat16* ol)
{
    const float* W; __nv_bfloat16 *th, *tl; int N;
    switch (blockIdx.z) {
        case 0:  W = Wq; th = qh; tl = ql; N = 2048; break;
        case 1:  W = Wk; th = kh; tl = kl; N = 512;  break;
        case 2:  W = Wv; th = vh; tl = vl; N = 512;  break;
        default: W = Wo; th = oh; tl = ol; N = 2048; break;
    }
    int n0 = blockIdx.x * 32, k0 = blockIdx.y * 32;
    if (n0 >= N) return;
    __shared__ float t[32][33];
    int tx = threadIdx.x & 31, ty = threadIdx.x >> 5;
#pragma unroll
    for (int j = 0; j < 32; j += 8)
        t[ty + j][tx] = W[(size_t)(k0 + ty + j) * N + n0 + tx];
    __syncthreads();
#pragma unroll
    for (int j = 0; j < 32; j += 8) {
        float v = t[tx][ty + j];
        __nv_bfloat16 h = __float2bfloat16(v);
        size_t o = (size_t)(n0 + ty + j) * KDIM + k0 + tx;
        th[o] = h;
        tl[o] = __float2bfloat16(v - __bfloat162float(h));
    }
}

// ---------------- mma.sync GEMM (unchanged from R8) ------------------------
template <bool HEAD>
__global__ __launch_bounds__(256)
void gemm_mma(const __nv_bfloat16* __restrict__ Ahi, const __nv_bfloat16* __restrict__ Alo,
              const __nv_bfloat16* __restrict__ Bhi, const __nv_bfloat16* __restrict__ Blo,
              float* __restrict__ C, int Nglob, int Hout)
{
    extern __shared__ __align__(16) char smem[];
    const uint32_t sb0 = cvta_s(smem);

    const int tid  = threadIdx.x;
    const int wid  = tid >> 5, lane = tid & 31;
    const int wm   = wid & 3,  wn   = wid >> 2;
    const int am   = wm * 32,  bn0  = wn * 64;
    const int bm   = blockIdx.y * 128, bn = blockIdx.x * 128;

    const __nv_bfloat16* srcs[4] = { Ahi + (size_t)bm * KDIM, Alo + (size_t)bm * KDIM,
                                     Bhi + (size_t)bn * KDIM, Blo + (size_t)bn * KDIM };

    const int lr[4] = { (tid + 0)   >> 3, (tid + 256) >> 3,
                        (tid + 512) >> 3, (tid + 768) >> 3 };
    const int lc[4] = { (tid + 0)   & 7,  (tid + 256) & 7,
                        (tid + 512) & 7,  (tid + 768) & 7 };

    float acc[2][8][4];
#pragma unroll
    for (int mi = 0; mi < 2; mi++)
#pragma unroll
        for (int ni = 0; ni < 8; ni++)
#pragma unroll
            for (int c = 0; c < 4; c++) acc[mi][ni][c] = 0.f;

    const int NT = KDIM / 64;

    auto load_stage = [&](int s, int kt) {
        uint32_t sb = sb0 + s * 65536;
#pragma unroll
        for (int tt = 0; tt < 4; tt++) {
            const __nv_bfloat16* src = srcs[tt];
#pragma unroll
            for (int a = 0; a < 4; a++) {
                int r = lr[a], c4 = lc[a];
                uint32_t dst = sb + tt * 16384 + r * 128 + ((c4 ^ (r & 7)) << 4);
                cp16(dst, src + (size_t)r * KDIM + kt + c4 * 8);
            }
        }
        asm volatile("cp.async.commit_group;" ::: "memory");
    };

    load_stage(0, 0);

    for (int it = 0; it < NT; ++it) {
        if (it + 1 < NT) {
            load_stage((it + 1) & 1, (it + 1) * 64);
            asm volatile("cp.async.wait_group 1;" ::: "memory");
        } else {
            asm volatile("cp.async.wait_group 0;" ::: "memory");
        }
        __syncthreads();

        const uint32_t sb = sb0 + (it & 1) * 65536;
#pragma unroll
        for (int ks = 0; ks < 4; ks++) {
            uint32_t ah[2][4], al[2][4], bh[8][2], bl[8][2];
#pragma unroll
            for (int mi = 0; mi < 2; mi++) {
                int r  = am + mi * 16 + (lane & 15);
                int c4 = ks * 2 + (lane >> 4);
                uint32_t off = r * 128 + ((c4 ^ (r & 7)) << 4);
                ldsm4(ah[mi], sb + off);
                ldsm4(al[mi], sb + 16384 + off);
            }
#pragma unroll
            for (int nb = 0; nb < 4; nb++) {
                int r  = bn0 + nb * 16 + (lane & 15);
                int c4 = ks * 2 + (lane >> 4);
                uint32_t off = r * 128 + ((c4 ^ (r & 7)) << 4);
                uint32_t t[4];
                ldsm4(t, sb + 32768 + off);
                bh[nb*2][0] = t[0]; bh[nb*2][1] = t[2];
                bh[nb*2+1][0] = t[1]; bh[nb*2+1][1] = t[3];
                ldsm4(t, sb + 49152 + off);
                bl[nb*2][0] = t[0]; bl[nb*2][1] = t[2];
                bl[nb*2+1][0] = t[1]; bl[nb*2+1][1] = t[3];
            }
#pragma unroll
            for (int mi = 0; mi < 2; mi++)
#pragma unroll
                for (int ni = 0; ni < 8; ni++) mma16816(acc[mi][ni], ah[mi], bh[ni]);
#pragma unroll
            for (int mi = 0; mi < 2; mi++)
#pragma unroll
                for (int ni = 0; ni < 8; ni++) mma16816(acc[mi][ni], al[mi], bh[ni]);
#pragma unroll
            for (int mi = 0; mi < 2; mi++)
#pragma unroll
                for (int ni = 0; ni < 8; ni++) mma16816(acc[mi][ni], ah[mi], bl[ni]);
        }
        __syncthreads();
    }

    const int g = lane >> 2, tig = lane & 3;
#pragma unroll
    for (int mi = 0; mi < 2; mi++) {
#pragma unroll
        for (int ni = 0; ni < 8; ni++) {
            int d   = bn0 + ni * 8 + tig * 2;
            int r0  = bm + am + mi * 16 + g;
            int r1  = r0 + 8;
            float* p0;
            float* p1;
            if (HEAD) {
                int h = bn >> 7;
                int b0 = r0 >> 10, n0 = r0 & 1023;
                int b1 = r1 >> 10, n1 = r1 & 1023;
                p0 = C + (((size_t)(b0 * Hout + h)) * NSEQ + n0) * DH + d;
                p1 = C + (((size_t)(b1 * Hout + h)) * NSEQ + n1) * DH + d;
            } else {
                p0 = C + (size_t)r0 * Nglob + bn + d;
                p1 = C + (size_t)r1 * Nglob + bn + d;
            }
            *(float2*)p0 = make_float2(acc[mi][ni][0], acc[mi][ni][1]);
            *(float2*)p1 = make_float2(acc[mi][ni][2], acc[mi][ni][3]);
        }
    }
}

// ---------------- rope table + apply (fp32 -> rotated bf16 hi/lo) ----------
__global__ void rope_table(float* __restrict__ cs)
{
    int idx = blockIdx.x * blockDim.x + threadIdx.x;
    if (idx >= NSEQ * 64) return;
    int i = idx & 63, n = idx >> 6;
    double invf = exp(-(double)i * 0.14391156831212787);
    double ang  = (double)n * invf;
    double s, c;
    sincos(ang, &s, &c);
    cs[idx * 2]     = (float)c;
    cs[idx * 2 + 1] = (float)s;
}
__global__ void rope_hl(const float* __restrict__ src, const float* __restrict__ cs,
                        __nv_bfloat16* __restrict__ hi, __nv_bfloat16* __restrict__ lo,
                        int total)
{
    int idx = blockIdx.x * blockDim.x + threadIdx.x;
    if (idx >= total) return;
    int i   = idx & 63;
    int n   = (idx >> 6) & 1023;
    int bhd = idx >> 16;
    float2 v = ((const float2*)cs)[n * 64 + i];
    size_t o0 = (size_t)bhd * (NSEQ * DH) + n * DH + i;
    float t1 = src[o0], t2 = src[o0 + 64];
    float r0 = t1 * v.x - t2 * v.y;
    float r1 = t2 * v.x + t1 * v.y;
    __nv_bfloat16 b0 = __float2bfloat16(r0);
    __nv_bfloat16 b1 = __float2bfloat16(r1);
    hi[o0]      = b0; lo[o0]      = __float2bfloat16(r0 - __bfloat162float(b0));
    hi[o0 + 64] = b1; lo[o0 + 64] = __float2bfloat16(r1 - __bfloat162float(b1));
}

// ---------------- tensor-core causal flash attention -----------------------
// 64x64 tiles, 4 warps (warp = 16 rows), bf16 hi/lo 3-pass for S and PV.
// smem (176KB): Qhi 0 |Qlo 16K |Khi/Klo x2 stages 32K..96K |Vhi/Vlo x2 98304..163840
//               |Phi 163840 |Plo 172032
__global__ __launch_bounds__(128)
void flash_tc(const __nv_bfloat16* __restrict__ Qh_, const __nv_bfloat16* __restrict__ Ql_,
              const __nv_bfloat16* __restrict__ Kh_, const __nv_bfloat16* __restrict__ Kl_,
              const __nv_bfloat16* __restrict__ Vh_, const __nv_bfloat16* __restrict__ Vl_,
              const float* __restrict__ hsc,
              __nv_bfloat16* __restrict__ Ohi, __nv_bfloat16* __restrict__ Olo)
{
    extern __shared__ __align__(16) char smc[];
    const uint32_t smb = cvta_s(smc);
    const int tid = threadIdx.x, wid = tid >> 5, lane = tid & 31;
    const int qb = 15 - blockIdx.x;                   // big q-blocks first
    const int bh = blockIdx.y, b = bh >> 4, h = bh & 15, kvh = h >> 2;
    const int m0 = wid * 16;
    const int g = lane >> 2, tig = lane & 3;
    const float scale = 0.08838834764831845f;

    const __nv_bfloat16* Qhg = Qh_ + ((size_t)(b * NH + h) * NSEQ + qb * 64) * DH;
    const __nv_bfloat16* Qlg = Ql_ + ((size_t)(b * NH + h) * NSEQ + qb * 64) * DH;
    const size_t kvb = (size_t)(b * NKV + kvh) * NSEQ * DH;

    // Q tiles (hi+lo) via cp.async
#pragma unroll
    for (int t = 0; t < 8; t++) {
        int e = tid + t * 128, r = e >> 4, c4 = e & 15;
        uint32_t off = r * 256 + (((c4 ^ (r & 7))) << 4);
        cp16(smb + off,         Qhg + r * DH + c4 * 8);
        cp16(smb + 16384 + off, Qlg + r * DH + c4 * 8);
    }
    auto ldkv = [&](int s, int kb) {
        const __nv_bfloat16* kh = Kh_ + kvb + (size_t)kb * 64 * DH;
        const __nv_bfloat16* kl = Kl_ + kvb + (size_t)kb * 64 * DH;
        const __nv_bfloat16* vh = Vh_ + kvb + (size_t)kb * 64 * DH;
        const __nv_bfloat16* vl = Vl_ + kvb + (size_t)kb * 64 * DH;
        uint32_t kd = smb + 32768 + s * 32768;
        uint32_t vd = smb + 98304 + s * 32768;
#pragma unroll
        for (int t = 0; t < 8; t++) {
            int e = tid + t * 128, r = e >> 4, c4 = e & 15;
            uint32_t off = r * 256 + (((c4 ^ (r & 7))) << 4);
            int go = r * DH + c4 * 8;
            cp16(kd + off,         kh + go);
            cp16(kd + 16384 + off, kl + go);
            cp16(vd + off,         vh + go);
            cp16(vd + 16384 + off, vl + go);
        }
        asm volatile("cp.async.commit_group;" ::: "memory");
    };
    ldkv(0, 0);   // commits Q + KV0 as one group

    float m_i[2] = {-1e30f, -1e30f}, l_i[2] = {0.f, 0.f};
    float o[16][4];
#pragma unroll
    for (int ni = 0; ni < 16; ni++)
#pragma unroll
        for (int c = 0; c < 4; c++) o[ni][c] = 0.f;

    for (int kb = 0; kb <= qb; ++kb) {
        asm volatile("cp.async.wait_group 0;" ::: "memory");
        __syncthreads();
        if (kb < qb) ldkv((kb + 1) & 1, kb + 1);

        const uint32_t sK = smb + 32768 + (kb & 1) * 32768;
        const uint32_t sV = smb + 98304 + (kb & 1) * 32768;

        // ---- S = Q K^T (3-pass hi/lo), warp tile 16x64 ----
        float sf[8][4];
#pragma unroll
        for (int ni = 0; ni < 8; ni++)
#pragma unroll
            for (int c = 0; c < 4; c++) sf[ni][c] = 0.f;

#pragma unroll
        for (int ks = 0; ks < 8; ks++) {
            uint32_t ah[4], al[4], bh2[8][2], bl2[8][2];
            {
                int r = m0 + (lane & 15), c4 = ks * 2 + (lane >> 4);
                uint32_t off = r * 256 + ((c4 ^ (r & 7)) << 4);
                ldsm4(ah, smb + off);
                ldsm4(al, smb + 16384 + off);
            }
#pragma unroll
            for (int nb = 0; nb < 4; nb++) {
                int r = nb * 16 + (lane & 15), c4 = ks * 2 + (lane >> 4);
                uint32_t off = r * 256 + ((c4 ^ (r & 7)) << 4);
                uint32_t t4r[4];
                ldsm4(t4r, sK + off);
                bh2[nb*2][0] = t4r[0]; bh2[nb*2][1] = t4r[2];
                bh2[nb*2+1][0] = t4r[1]; bh2[nb*2+1][1] = t4r[3];
                ldsm4(t4r, sK + 16384 + off);
                bl2[nb*2][0] = t4r[0]; bl2[nb*2][1] = t4r[2];
                bl2[nb*2+1][0] = t4r[1]; bl2[nb*2+1][1] = t4r[3];
            }
#pragma unroll
            for (int ni = 0; ni < 8; ni++) mma16816(sf[ni], ah, bh2[ni]);
#pragma unroll
            for (int ni = 0; ni < 8; ni++) mma16816(sf[ni], al, bh2[ni]);
#pragma unroll
            for (int ni = 0; ni < 8; ni++) mma16816(sf[ni], ah, bl2[ni]);
        }

        // ---- online softmax (per-warp; rows g, g+8 of warp's 16) ----
        const bool diag = (kb == qb);
#pragma unroll
        for (int rr = 0; rr < 2; rr++) {
            int lr = m0 + g + rr * 8;
            float mx = -1e30f;
#pragma unroll
            for (int ni = 0; ni < 8; ni++)
#pragma unroll
                for (int c = 0; c < 2; c++) {
                    float v = sf[ni][rr * 2 + c] * scale;
                    if (diag && (ni * 8 + tig * 2 + c) > lr) v = -1e30f;
                    sf[ni][rr * 2 + c] = v;
                    mx = fmaxf(mx, v);
                }
            mx = fmaxf(mx, __shfl_xor_sync(0xffffffffu, mx, 1));
            mx = fmaxf(mx, __shfl_xor_sync(0xffffffffu, mx, 2));
            float mn    = fmaxf(m_i[rr], mx);
            float alpha = __expf(m_i[rr] - mn);
            m_i[rr] = mn;
            float rs = 0.f;
#pragma unroll
            for (int ni = 0; ni < 8; ni++)
#pragma unroll
                for (int c = 0; c < 2; c++) {
                    float p = __expf(sf[ni][rr * 2 + c] - mn);
                    sf[ni][rr * 2 + c] = p;
                    rs += p;
                }
            rs += __shfl_xor_sync(0xffffffffu, rs, 1);
            rs += __shfl_xor_sync(0xffffffffu, rs, 2);
            l_i[rr] = l_i[rr] * alpha + rs;
#pragma unroll
            for (int ni = 0; ni < 16; ni++) {
                o[ni][rr * 2]     *= alpha;
                o[ni][rr * 2 + 1] *= alpha;
            }
        }

        // ---- store P hi/lo to smem (own warp rows only) ----
        __syncwarp();
#pragma unroll
        for (int ni = 0; ni < 8; ni++)
#pragma unroll
            for (int rr = 0; rr < 2; rr++) {
                int r = m0 + g + rr * 8;
                uint32_t off = r * 128 + ((ni ^ (r & 7)) << 4) + tig * 4;
                float p0 = sf[ni][rr * 2], p1 = sf[ni][rr * 2 + 1];
                __nv_bfloat16 h0 = __float2bfloat16(p0), h1 = __float2bfloat16(p1);
                *(__nv_bfloat162*)(smc + 163840 + off) = __nv_bfloat162(h0, h1);
                *(__nv_bfloat162*)(smc + 172032 + off) =
                    __nv_bfloat162(__float2bfloat16(p0 - __bfloat162float(h0)),
                                   __float2bfloat16(p1 - __bfloat162float(h1)));
            }
        __syncwarp();

        // ---- O += P V (3-pass), warp tile 16x128 ----
#pragma unroll
        for (int ks = 0; ks < 4; ks++) {
            uint32_t ph[4], pl[4];
            {
                int r = m0 + (lane & 15), c3 = ks * 2 + (lane >> 4);
                uint32_t off = r * 128 + ((c3 ^ (r & 7)) << 4);
                ldsm4(ph, smb + 163840 + off);
                ldsm4(pl, smb + 172032 + off);
            }
#pragma unroll
            for (int nb = 0; nb < 8; nb++) {
                int row = ks * 16 + (lane & 7) + ((lane & 16) >> 1);
                int ch  = nb * 2 + ((lane >> 3) & 1);
                uint32_t off = row * 256 + ((ch ^ (row & 7)) << 4);
                uint32_t t4r[4], bvh[2][2], bvl[2][2];
                ldsm4t(t4r, sV + off);
                bvh[0][0] = t4r[0]; bvh[0][1] = t4r[2];
                bvh[1][0] = t4r[1]; bvh[1][1] = t4r[3];
                ldsm4t(t4r, sV + 16384 + off);
                bvl[0][0] = t4r[0]; bvl[0][1] = t4r[2];
                bvl[1][0] = t4r[1]; bvl[1][1] = t4r[3];
                mma16816(o[nb*2],   ph, bvh[0]);
                mma16816(o[nb*2+1], ph, bvh[1]);
                mma16816(o[nb*2],   pl, bvh[0]);
                mma16816(o[nb*2+1], pl, bvh[1]);
                mma16816(o[nb*2],   ph, bvl[0]);
                mma16816(o[nb*2+1], ph, bvl[1]);
            }
        }
    }

    // ---- epilogue: normalize, head-scale, write bf16 hi/lo O ----
    const float hval = hsc[h];
#pragma unroll
    for (int rr = 0; rr < 2; rr++) {
        float inv = hval / l_i[rr];
        int n = qb * 64 + m0 + g + rr * 8;
        size_t base = ((size_t)(b * NSEQ + n)) * DIMM + h * DH;
#pragma unroll
        for (int ni = 0; ni < 16; ni++) {
            int col = ni * 8 + tig * 2;
            float v0 = o[ni][rr * 2] * inv, v1 = o[ni][rr * 2 + 1] * inv;
            __nv_bfloat16 h0 = __float2bfloat16(v0), h1 = __float2bfloat16(v1);
            *(__nv_bfloat162*)(Ohi + base + col) = __nv_bfloat162(h0, h1);
            *(__nv_bfloat162*)(Olo + base + col) =
                __nv_bfloat162(__float2bfloat16(v0 - __bfloat162float(h0)),
                               __float2bfloat16(v1 - __bfloat162float(h1)));
        }
    }
}

// ---------------- launch ---------------------------------------------------
extern "C" void kernel_launch(void* const* d_in, const int* in_sizes, int n_in,
                              void* d_out, int out_size)
{
    const float* x   = (const float*)d_in[0];
    const float* Wq  = (const float*)d_in[1];
    const float* Wk  = (const float*)d_in[2];
    const float* Wv  = (const float*)d_in[3];
    const float* Wo  = (const float*)d_in[4];
    const float* hsc = (const float*)d_in[5];
    float* out = (float*)d_out;

    float *Qh, *Kh, *Vh, *cs;
    __nv_bfloat16 *xhi, *xlo, *Wqh, *Wql, *Wkh, *Wkl, *Wvh, *Wvl, *Woh, *Wol, *Ohi, *Olo;
    __nv_bfloat16 *Qbh, *Qbl, *Kbh, *Kbl, *Vbh, *Vbl;
    cudaGetSymbolAddress((void**)&Qh,  g_Qh);
    cudaGetSymbolAddress((void**)&Kh,  g_Kh);
    cudaGetSymbolAddress((void**)&Vh,  g_Vh);
    cudaGetSymbolAddress((void**)&cs,  g_cs);
    cudaGetSymbolAddress((void**)&xhi, g_xhi);  cudaGetSymbolAddress((void**)&xlo, g_xlo);
    cudaGetSymbolAddress((void**)&Wqh, g_Wqh);  cudaGetSymbolAddress((void**)&Wql, g_Wql);
    cudaGetSymbolAddress((void**)&Wkh, g_Wkh);  cudaGetSymbolAddress((void**)&Wkl, g_Wkl);
    cudaGetSymbolAddress((void**)&Wvh, g_Wvh);  cudaGetSymbolAddress((void**)&Wvl, g_Wvl);
    cudaGetSymbolAddress((void**)&Woh, g_Woh);  cudaGetSymbolAddress((void**)&Wol, g_Wol);
    cudaGetSymbolAddress((void**)&Ohi, g_Ohi);  cudaGetSymbolAddress((void**)&Olo, g_Olo);
    cudaGetSymbolAddress((void**)&Qbh, g_Qbh);  cudaGetSymbolAddress((void**)&Qbl, g_Qbl);
    cudaGetSymbolAddress((void**)&Kbh, g_Kbh);  cudaGetSymbolAddress((void**)&Kbl, g_Kbl);
    cudaGetSymbolAddress((void**)&Vbh, g_Vbh);  cudaGetSymbolAddress((void**)&Vbl, g_Vbl);

    // 1..3: prep  (launch order matters: ncu -s 5 -c 1 captures launch #6 = gemmQ)
    rope_table<<<(NSEQ * 64 + 255) / 256, 256>>>(cs);
    prep_split<<<(MTOT * KDIM / 4 + 255) / 256, 256>>>(x, xhi, xlo, MTOT * KDIM / 4);
    wtrans_all<<<dim3(64, 64, 4), 256>>>(Wq, Wk, Wv, Wo, Wqh, Wql, Wkh, Wkl,
                                         Wvh, Wvl, Woh, Wol);

    // 4..6: projections (Q last so it is the profiled launch)
    const int gsm = 131072;
    cudaFuncSetAttribute(gemm_mma<true>,  cudaFuncAttributeMaxDynamicSharedMemorySize, gsm);
    cudaFuncSetAttribute(gemm_mma<false>, cudaFuncAttributeMaxDynamicSharedMemorySize, gsm);
    gemm_mma<true><<<dim3(4,  32), 256, gsm>>>(xhi, xlo, Wkh, Wkl, Kh, 512,  NKV);
    gemm_mma<true><<<dim3(4,  32), 256, gsm>>>(xhi, xlo, Wvh, Wvl, Vh, 512,  NKV);
    gemm_mma<true><<<dim3(16, 32), 256, gsm>>>(xhi, xlo, Wqh, Wql, Qh, 2048, NH);

    // 7..9: rope -> bf16 hi/lo, V split
    int ropeQ = NH  * B_SZ * NSEQ * 64;
    int ropeK = NKV * B_SZ * NSEQ * 64;
    rope_hl<<<ropeQ / 256, 256>>>(Qh, cs, Qbh, Qbl, ropeQ);
    rope_hl<<<ropeK / 256, 256>>>(Kh, cs, Kbh, Kbl, ropeK);
    prep_split<<<(B_SZ * NKV * NSEQ * DH / 4 + 255) / 256, 256>>>(
        Vh, Vbh, Vbl, B_SZ * NKV * NSEQ * DH / 4);

    // 10: tensor-core flash attention
    const int fsm = 180224;
    cudaFuncSetAttribute(flash_tc, cudaFuncAttributeMaxDynamicSharedMemorySize, fsm);
    flash_tc<<<dim3(16, B_SZ * NH), 128, fsm>>>(Qbh, Qbl, Kbh, Kbl, Vbh, Vbl,
                                                hsc, Ohi, Olo);

    // 11: output projection
    gemm_mma<false><<<dim3(16, 32), 256, gsm>>>(Ohi, Olo, Woh, Wol, out, 2048, 0);
}